// round 1
// baseline (speedup 1.0000x reference)
#include <cuda_runtime.h>
#include <stdint.h>
#include <math.h>

#define NB 4096  // batch

// ------------------------------------------------------------------
// scratch (single __device__ global, offsets in floats)
// ------------------------------------------------------------------
__device__ float g_scratch[36446208];

#define OFF_X1    0          // 4096*3584
#define OFF_X2    14680064   // 4096*1408
#define OFF_X3    20447232   // 4096*512
#define OFF_GATES 22544384   // 4096*2048
#define OFF_ZA    30932992   // 4096*512
#define OFF_ZB    33030144   // 4096*512
#define OFF_Z1    35127296   // 4096*256
#define OFF_LOG   36175872   // 4096*64
#define OFF_ACT   36438016   // 4096
#define OFF_ENT   36442112   // 4096

// ------------------------------------------------------------------
// threefry2x32 (JAX-compatible, 20 rounds)
// ------------------------------------------------------------------
__host__ __device__ __forceinline__ void threefry2x32(
    uint32_t k0, uint32_t k1, uint32_t x0, uint32_t x1,
    uint32_t* o0, uint32_t* o1)
{
    uint32_t ks0 = k0, ks1 = k1, ks2 = 0x1BD11BDAu ^ k0 ^ k1;
    x0 += ks0; x1 += ks1;
#define TF_ROUND(r) do { x0 += x1; x1 = (x1 << (r)) | (x1 >> (32 - (r))); x1 ^= x0; } while (0)
    TF_ROUND(13); TF_ROUND(15); TF_ROUND(26); TF_ROUND(6);
    x0 += ks1; x1 += ks2 + 1u;
    TF_ROUND(17); TF_ROUND(29); TF_ROUND(16); TF_ROUND(24);
    x0 += ks2; x1 += ks0 + 2u;
    TF_ROUND(13); TF_ROUND(15); TF_ROUND(26); TF_ROUND(6);
    x0 += ks0; x1 += ks1 + 3u;
    TF_ROUND(17); TF_ROUND(29); TF_ROUND(16); TF_ROUND(24);
    x0 += ks1; x1 += ks2 + 4u;
    TF_ROUND(13); TF_ROUND(15); TF_ROUND(26); TF_ROUND(6);
    x0 += ks2; x1 += ks0 + 5u;
#undef TF_ROUND
    *o0 = x0; *o1 = x1;
}

// partitionable-mode 32-bit random bits for flat element j (counter (0, j))
__device__ __forceinline__ float gumbel_for(uint32_t k0, uint32_t k1, uint32_t j)
{
    uint32_t o0, o1;
    threefry2x32(k0, k1, 0u, j, &o0, &o1);
    uint32_t bits = o0 ^ o1;
    uint32_t fb = (bits >> 9) | 0x3f800000u;
    float f = __uint_as_float(fb) - 1.0f;            // [0, 1)
    if (f == 0.0f) f = 1.1754943508222875e-38f;      // minval = tiny
    return -logf(-logf(f));
}

// ------------------------------------------------------------------
// generic SGEMM: C[4096, N] = epilogue(A @ B + bias (+ bias2) (+ C))
//   mode 0: A plain row-major, lda
//   mode 1: A = concat(actual[4608], objective[4608], last[8], ep[1])
//   mode 2: A = concat(z[512], act[1])   (K = 513)
//   B element (k,n) at B[k*ldbk + n*ldbn]
//   flags: 1 = relu, 2 = accumulate into C
// ------------------------------------------------------------------
#define BM 128
#define BN 128
#define BK 8
#define TM 8
#define TN 8

__global__ void __launch_bounds__(256)
sgemm(const float* __restrict__ A, int lda,
      const float* __restrict__ B, int ldbk, int ldbn,
      const float* __restrict__ bias, const float* __restrict__ bias2,
      float* __restrict__ C, int N, int K, int flags, int mode,
      const float* __restrict__ s0, const float* __restrict__ s1,
      const float* __restrict__ s2, const int* __restrict__ epPtr,
      const float* __restrict__ actPtr)
{
    __shared__ float As[BK][BM];
    __shared__ float Bs[BK][BN];

    const int tid = threadIdx.x;
    const int bm = blockIdx.y * BM;
    const int bn = blockIdx.x * BN;
    const int tx = tid & 15;
    const int ty = tid >> 4;

    float ep = 0.0f;
    if (mode == 1 && epPtr) ep = (float)(*epPtr);

    float acc[TM][TN];
#pragma unroll
    for (int i = 0; i < TM; i++)
#pragma unroll
        for (int j = 0; j < TN; j++) acc[i][j] = 0.0f;

    const int am = tid >> 1;           // A row in tile
    const int ak = (tid & 1) * 4;      // A k-phase
    const int bk = tid >> 5;           // B k row in tile
    const int bn0 = (tid & 31) * 4;    // B n base

    for (int kt = 0; kt < K; kt += BK) {
        // --- load A tile (gathered) ---
#pragma unroll
        for (int i = 0; i < 4; i++) {
            int k = kt + ak + i;
            int m = bm + am;
            float v = 0.0f;
            if (k < K) {
                if (mode == 0) {
                    v = A[(size_t)m * lda + k];
                } else if (mode == 1) {
                    if (k < 4608)      v = s0[(size_t)m * 4608 + k];
                    else if (k < 9216) v = s1[(size_t)m * 4608 + (k - 4608)];
                    else if (k < 9224) v = s2[m * 8 + (k - 9216)];
                    else               v = ep;
                } else {
                    v = (k < 512) ? A[(size_t)m * 512 + k] : actPtr[m];
                }
            }
            As[ak + i][am] = v;
        }
        // --- load B tile ---
#pragma unroll
        for (int i = 0; i < 4; i++) {
            int k = kt + bk;
            int n = bn + bn0 + i;
            float v = 0.0f;
            if (k < K && n < N) v = B[(size_t)k * ldbk + (size_t)n * ldbn];
            Bs[bk][bn0 + i] = v;
        }
        __syncthreads();

#pragma unroll
        for (int kk = 0; kk < BK; kk++) {
            float a[TM], b[TN];
#pragma unroll
            for (int i = 0; i < TM; i++) a[i] = As[kk][ty * TM + i];
#pragma unroll
            for (int j = 0; j < TN; j++) b[j] = Bs[kk][tx * TN + j];
#pragma unroll
            for (int i = 0; i < TM; i++)
#pragma unroll
                for (int j = 0; j < TN; j++)
                    acc[i][j] = fmaf(a[i], b[j], acc[i][j]);
        }
        __syncthreads();
    }

    // --- epilogue ---
#pragma unroll
    for (int i = 0; i < TM; i++) {
        int m = bm + ty * TM + i;
#pragma unroll
        for (int j = 0; j < TN; j++) {
            int n = bn + tx * TN + j;
            if (n < N) {
                float v = acc[i][j];
                if (bias)  v += bias[n];
                if (bias2) v += bias2[n];
                if (flags & 2) v += C[(size_t)m * N + n];
                if (flags & 1) v = fmaxf(v, 0.0f);
                C[(size_t)m * N + n] = v;
            }
        }
    }
}

// ------------------------------------------------------------------
// LSTM pointwise (torch gate order i,f,g,o)
// ------------------------------------------------------------------
__global__ void lstm_kernel(const float* __restrict__ gates,
                            const float* __restrict__ c0,
                            float* __restrict__ z)
{
    int i = blockIdx.x * blockDim.x + threadIdx.x;
    if (i >= NB * 512) return;
    int b = i >> 9, c = i & 511;
    const float* gr = gates + (size_t)b * 2048;
    float gi = gr[c], gf = gr[512 + c], gg = gr[1024 + c], go = gr[1536 + c];
    float si = 1.0f / (1.0f + expf(-gi));
    float sf = 1.0f / (1.0f + expf(-gf));
    float so = 1.0f / (1.0f + expf(-go));
    float cc = sf * c0[i] + si * tanhf(gg);
    z[i] = so * tanhf(cc);
}

// ------------------------------------------------------------------
// per-row softmax + gumbel-argmax sampling (one warp per row)
// ------------------------------------------------------------------
__global__ void sample_kernel(const float* __restrict__ logits,
                              float* __restrict__ actBuf,
                              float* __restrict__ outAction,
                              float* __restrict__ lpAcc,
                              float* __restrict__ entAcc,
                              uint32_t sk0, uint32_t sk1, int head)
{
    int warp = (blockIdx.x * blockDim.x + threadIdx.x) >> 5;
    int lane = threadIdx.x & 31;
    if (warp >= NB) return;
    int r = warp;

    float x0 = logits[r * 64 + lane];
    float x1 = logits[r * 64 + 32 + lane];

    float mx = fmaxf(x0, x1);
#pragma unroll
    for (int o = 16; o; o >>= 1) mx = fmaxf(mx, __shfl_xor_sync(0xffffffffu, mx, o));

    float s = expf(x0 - mx) + expf(x1 - mx);
#pragma unroll
    for (int o = 16; o; o >>= 1) s += __shfl_xor_sync(0xffffffffu, s, o);
    float lse = mx + logf(s);

    // entropy term: sum p * (lse - x) = -sum p*logp
    float t = expf(x0 - lse) * (lse - x0) + expf(x1 - lse) * (lse - x1);
#pragma unroll
    for (int o = 16; o; o >>= 1) t += __shfl_xor_sync(0xffffffffu, t, o);

    // gumbel-argmax
    float g0 = gumbel_for(sk0, sk1, (uint32_t)(r * 64 + lane));
    float g1 = gumbel_for(sk0, sk1, (uint32_t)(r * 64 + 32 + lane));
    float ya = x0 + g0, yb = x1 + g1;
    float y; int idx;
    if (ya >= yb) { y = ya; idx = lane; } else { y = yb; idx = lane + 32; }
#pragma unroll
    for (int o = 16; o; o >>= 1) {
        float oy = __shfl_xor_sync(0xffffffffu, y, o);
        int   oi = __shfl_xor_sync(0xffffffffu, idx, o);
        if (oy > y || (oy == y && oi < idx)) { y = oy; idx = oi; }
    }

    int src = idx & 31;
    float v0 = __shfl_sync(0xffffffffu, x0, src);
    float v1 = __shfl_sync(0xffffffffu, x1, src);
    float xw = (idx < 32) ? v0 : v1;

    if (lane == 0) {
        actBuf[r] = (float)idx;
        outAction[r * 8 + head] = (float)idx;
        lpAcc[r] += xw - lse;
        entAcc[r] += t;
    }
}

__global__ void init_kernel(float* __restrict__ lp, float* __restrict__ ent)
{
    int i = blockIdx.x * blockDim.x + threadIdx.x;
    if (i < NB) { lp[i] = 0.0f; ent[i] = 0.0f; }
}

__global__ void reduce_ent(const float* __restrict__ ent, float* __restrict__ out)
{
    __shared__ float sm[256];
    float s = 0.0f;
    for (int i = threadIdx.x; i < NB; i += 256) s += ent[i];
    sm[threadIdx.x] = s;
    __syncthreads();
    for (int o = 128; o; o >>= 1) {
        if (threadIdx.x < o) sm[threadIdx.x] += sm[threadIdx.x + o];
        __syncthreads();
    }
    if (threadIdx.x == 0) out[0] = sm[0];
}

// ------------------------------------------------------------------
// host launcher
// ------------------------------------------------------------------
extern "C" void kernel_launch(void* const* d_in, const int* in_sizes, int n_in,
                              void* d_out, int out_size)
{
    const float* actual    = (const float*)d_in[0];
    const float* objective = (const float*)d_in[1];
    const float* last      = (const float*)d_in[2];

    // episode_percentage may or may not be materialized as an input
    int base = 4;
    const int* epPtr = nullptr;
    if (in_sizes[3] == 1) epPtr = (const int*)d_in[3];
    else base = 3;

    const float* W1  = (const float*)d_in[base + 0];
    const float* b1  = (const float*)d_in[base + 1];
    const float* W2  = (const float*)d_in[base + 2];
    const float* b2  = (const float*)d_in[base + 3];
    const float* W3  = (const float*)d_in[base + 4];
    const float* b3  = (const float*)d_in[base + 5];
    const float* Wih = (const float*)d_in[base + 6];
    const float* Whh = (const float*)d_in[base + 7];
    const float* bih = (const float*)d_in[base + 8];
    const float* bhh = (const float*)d_in[base + 9];
    const float* h0  = (const float*)d_in[base + 10];
    const float* c0  = (const float*)d_in[base + 11];
    const float* dW1 = (const float*)d_in[base + 12];
    const float* db1 = (const float*)d_in[base + 13];

    const float* headW[8];
    const float* headb[8];
    const float* dWo;
    const float* dbo;
    if (n_in >= base + 32) {  // tuples flattened into separate inputs
        for (int i = 0; i < 8; i++) {
            headW[i] = (const float*)d_in[base + 14 + i];
            headb[i] = (const float*)d_in[base + 22 + i];
        }
        dWo = (const float*)d_in[base + 30];
        dbo = (const float*)d_in[base + 31];
    } else {                  // tuples stacked
        const float* hw = (const float*)d_in[base + 14];
        const float* hb = (const float*)d_in[base + 15];
        for (int i = 0; i < 8; i++) {
            headW[i] = hw + (size_t)i * 256 * 64;
            headb[i] = hb + (size_t)i * 64;
        }
        dWo = (const float*)d_in[base + 16];
        dbo = (const float*)d_in[base + 17];
    }

    const int D1 = in_sizes[base + 1];  // b1 length
    const int D2 = in_sizes[base + 3];  // b2 length

    float* scratch = nullptr;
    cudaGetSymbolAddress((void**)&scratch, g_scratch);
    float* x1v   = scratch + OFF_X1;
    float* x2v   = scratch + OFF_X2;
    float* x3v   = scratch + OFF_X3;
    float* gates = scratch + OFF_GATES;
    float* za    = scratch + OFF_ZA;
    float* zb    = scratch + OFF_ZB;
    float* z1b   = scratch + OFF_Z1;
    float* logb  = scratch + OFF_LOG;
    float* actb  = scratch + OFF_ACT;
    float* entb  = scratch + OFF_ENT;

    float* out  = (float*)d_out;
    float* lp   = out + NB * 8 + 1;   // log_probabilities
    float* entO = out + NB * 8;       // entropy scalar

    // --- JAX key chain (partitionable / fold-like split), host side ---
    uint32_t k0 = 0u, k1 = 42u, sk0[8], sk1[8];
    for (int t = 0; t < 8; t++) {
        uint32_t n0, n1, s0, s1;
        threefry2x32(k0, k1, 0u, 0u, &n0, &n1);  // new key
        threefry2x32(k0, k1, 0u, 1u, &s0, &s1);  // subkey for this head
        sk0[t] = s0; sk1[t] = s1;
        k0 = n0; k1 = n1;
    }

    dim3 blk(256);
    const int MBLK = NB / BM;  // 32

    init_kernel<<<(NB + 255) / 256, blk>>>(lp, entb);

    // encoder
    sgemm<<<dim3((D1 + BN - 1) / BN, MBLK), blk>>>(
        nullptr, 0, W1, D1, 1, b1, nullptr, x1v, D1, 9225, 1, 1,
        actual, objective, last, epPtr, nullptr);
    sgemm<<<dim3((D2 + BN - 1) / BN, MBLK), blk>>>(
        x1v, D1, W2, D2, 1, b2, nullptr, x2v, D2, D1, 1, 0,
        nullptr, nullptr, nullptr, nullptr, nullptr);
    sgemm<<<dim3(4, MBLK), blk>>>(
        x2v, D2, W3, 512, 1, b3, nullptr, x3v, 512, D2, 1, 0,
        nullptr, nullptr, nullptr, nullptr, nullptr);

    // LSTM gates: x @ Wih^T + bih + bhh, then += h0 @ Whh^T
    sgemm<<<dim3(16, MBLK), blk>>>(
        x3v, 512, Wih, 1, 512, bih, bhh, gates, 2048, 512, 0, 0,
        nullptr, nullptr, nullptr, nullptr, nullptr);
    sgemm<<<dim3(16, MBLK), blk>>>(
        h0, 512, Whh, 1, 512, nullptr, nullptr, gates, 2048, 512, 2, 0,
        nullptr, nullptr, nullptr, nullptr, nullptr);
    lstm_kernel<<<(NB * 512 + 255) / 256, blk>>>(gates, c0, za);

    // autoregressive decoder
    for (int t = 0; t < 8; t++) {
        float* zin  = (t & 1) ? zb : za;
        float* zout = (t & 1) ? za : zb;

        sgemm<<<dim3(2, MBLK), blk>>>(
            zin, 512, dW1, 256, 1, db1, nullptr, z1b, 256, 512, 1, 0,
            nullptr, nullptr, nullptr, nullptr, nullptr);
        sgemm<<<dim3(1, MBLK), blk>>>(
            z1b, 256, headW[t], 64, 1, headb[t], nullptr, logb, 64, 256, 0, 0,
            nullptr, nullptr, nullptr, nullptr, nullptr);
        sample_kernel<<<NB / 8, blk>>>(logb, actb, out, lp, entb,
                                       sk0[t], sk1[t], t);
        sgemm<<<dim3(4, MBLK), blk>>>(
            zin, 512, dWo, 512, 1, dbo, nullptr, zout, 512, 513, 1, 2,
            nullptr, nullptr, nullptr, nullptr, actb);
    }

    reduce_ent<<<1, blk>>>(entb, entO);
}

// round 2
// speedup vs baseline: 1.0073x; 1.0073x over previous
#include <cuda_runtime.h>
#include <stdint.h>
#include <math.h>

#define NB 4096  // batch

// ------------------------------------------------------------------
// scratch (single __device__ global, offsets in floats)
// ------------------------------------------------------------------
__device__ float g_scratch[36446208];

#define OFF_X1    0          // 4096*3584
#define OFF_X2    14680064   // 4096*1408
#define OFF_X3    20447232   // 4096*512
#define OFF_GATES 22544384   // 4096*2048
#define OFF_ZA    30932992   // 4096*512
#define OFF_ZB    33030144   // 4096*512
#define OFF_Z1    35127296   // 4096*256
#define OFF_LOG   36175872   // 4096*64
#define OFF_ACT   36438016   // 4096
#define OFF_ENT   36442112   // 4096

// ------------------------------------------------------------------
// threefry2x32 (JAX-compatible, 20 rounds)
// ------------------------------------------------------------------
__host__ __device__ __forceinline__ void threefry2x32(
    uint32_t k0, uint32_t k1, uint32_t x0, uint32_t x1,
    uint32_t* o0, uint32_t* o1)
{
    uint32_t ks0 = k0, ks1 = k1, ks2 = 0x1BD11BDAu ^ k0 ^ k1;
    x0 += ks0; x1 += ks1;
#define TF_ROUND(r) do { x0 += x1; x1 = (x1 << (r)) | (x1 >> (32 - (r))); x1 ^= x0; } while (0)
    TF_ROUND(13); TF_ROUND(15); TF_ROUND(26); TF_ROUND(6);
    x0 += ks1; x1 += ks2 + 1u;
    TF_ROUND(17); TF_ROUND(29); TF_ROUND(16); TF_ROUND(24);
    x0 += ks2; x1 += ks0 + 2u;
    TF_ROUND(13); TF_ROUND(15); TF_ROUND(26); TF_ROUND(6);
    x0 += ks0; x1 += ks1 + 3u;
    TF_ROUND(17); TF_ROUND(29); TF_ROUND(16); TF_ROUND(24);
    x0 += ks1; x1 += ks2 + 4u;
    TF_ROUND(13); TF_ROUND(15); TF_ROUND(26); TF_ROUND(6);
    x0 += ks2; x1 += ks0 + 5u;
#undef TF_ROUND
    *o0 = x0; *o1 = x1;
}

// partitionable-mode 32-bit random bits for flat element j (counter (0, j))
__device__ __forceinline__ float gumbel_for(uint32_t k0, uint32_t k1, uint32_t j)
{
    uint32_t o0, o1;
    threefry2x32(k0, k1, 0u, j, &o0, &o1);
    uint32_t bits = o0 ^ o1;
    uint32_t fb = (bits >> 9) | 0x3f800000u;
    float f = __uint_as_float(fb) - 1.0f;            // [0, 1)
    if (f == 0.0f) f = 1.1754943508222875e-38f;      // minval = tiny
    return -logf(-logf(f));
}

// ------------------------------------------------------------------
// generic SGEMM: C[4096, N] = epilogue(A @ B + bias (+ bias2) (+ C))
//   mode 0: A plain row-major, lda
//   mode 1: A = concat(actual[4608], objective[4608], last[8], ep[1])
//   mode 2: A = concat(z[512], act[1])   (K = 513)
//   B element (k,n) at B[k*ldbk + n*ldbn]
//   flags: 1 = relu, 2 = accumulate into C
// ------------------------------------------------------------------
#define BM 128
#define BN 128
#define BK 8
#define TM 8
#define TN 8

__global__ void __launch_bounds__(256)
sgemm(const float* __restrict__ A, int lda,
      const float* __restrict__ B, int ldbk, int ldbn,
      const float* __restrict__ bias, const float* __restrict__ bias2,
      float* __restrict__ C, int N, int K, int flags, int mode,
      const float* __restrict__ s0, const float* __restrict__ s1,
      const float* __restrict__ s2, const int* __restrict__ epPtr,
      const float* __restrict__ actPtr)
{
    __shared__ float As[BK][BM];
    __shared__ float Bs[BK][BN];

    const int tid = threadIdx.x;
    const int bm = blockIdx.y * BM;
    const int bn = blockIdx.x * BN;
    const int tx = tid & 15;
    const int ty = tid >> 4;

    float ep = 0.0f;
    if (mode == 1 && epPtr) ep = (float)(*epPtr);

    float acc[TM][TN];
#pragma unroll
    for (int i = 0; i < TM; i++)
#pragma unroll
        for (int j = 0; j < TN; j++) acc[i][j] = 0.0f;

    const int am = tid >> 1;           // A row in tile
    const int ak = (tid & 1) * 4;      // A k-phase
    const int bk = tid >> 5;           // B k row in tile
    const int bn0 = (tid & 31) * 4;    // B n base

    for (int kt = 0; kt < K; kt += BK) {
        // --- load A tile (gathered) ---
#pragma unroll
        for (int i = 0; i < 4; i++) {
            int k = kt + ak + i;
            int m = bm + am;
            float v = 0.0f;
            if (k < K) {
                if (mode == 0) {
                    v = A[(size_t)m * lda + k];
                } else if (mode == 1) {
                    if (k < 4608)      v = s0[(size_t)m * 4608 + k];
                    else if (k < 9216) v = s1[(size_t)m * 4608 + (k - 4608)];
                    else if (k < 9224) v = s2[m * 8 + (k - 9216)];
                    else               v = ep;
                } else {
                    v = (k < 512) ? A[(size_t)m * 512 + k] : actPtr[m];
                }
            }
            As[ak + i][am] = v;
        }
        // --- load B tile ---
#pragma unroll
        for (int i = 0; i < 4; i++) {
            int k = kt + bk;
            int n = bn + bn0 + i;
            float v = 0.0f;
            if (k < K && n < N) v = B[(size_t)k * ldbk + (size_t)n * ldbn];
            Bs[bk][bn0 + i] = v;
        }
        __syncthreads();

#pragma unroll
        for (int kk = 0; kk < BK; kk++) {
            float a[TM], b[TN];
#pragma unroll
            for (int i = 0; i < TM; i++) a[i] = As[kk][ty * TM + i];
#pragma unroll
            for (int j = 0; j < TN; j++) b[j] = Bs[kk][tx * TN + j];
#pragma unroll
            for (int i = 0; i < TM; i++)
#pragma unroll
                for (int j = 0; j < TN; j++)
                    acc[i][j] = fmaf(a[i], b[j], acc[i][j]);
        }
        __syncthreads();
    }

    // --- epilogue ---
#pragma unroll
    for (int i = 0; i < TM; i++) {
        int m = bm + ty * TM + i;
#pragma unroll
        for (int j = 0; j < TN; j++) {
            int n = bn + tx * TN + j;
            if (n < N) {
                float v = acc[i][j];
                if (bias)  v += bias[n];
                if (bias2) v += bias2[n];
                if (flags & 2) v += C[(size_t)m * N + n];
                if (flags & 1) v = fmaxf(v, 0.0f);
                C[(size_t)m * N + n] = v;
            }
        }
    }
}

// ------------------------------------------------------------------
// LSTM pointwise (torch gate order i,f,g,o)
// ------------------------------------------------------------------
__global__ void lstm_kernel(const float* __restrict__ gates,
                            const float* __restrict__ c0,
                            float* __restrict__ z)
{
    int i = blockIdx.x * blockDim.x + threadIdx.x;
    if (i >= NB * 512) return;
    int b = i >> 9, c = i & 511;
    const float* gr = gates + (size_t)b * 2048;
    float gi = gr[c], gf = gr[512 + c], gg = gr[1024 + c], go = gr[1536 + c];
    float si = 1.0f / (1.0f + expf(-gi));
    float sf = 1.0f / (1.0f + expf(-gf));
    float so = 1.0f / (1.0f + expf(-go));
    float cc = sf * c0[i] + si * tanhf(gg);
    z[i] = so * tanhf(cc);
}

// ------------------------------------------------------------------
// per-row softmax + gumbel-argmax sampling (one warp per row)
// ------------------------------------------------------------------
__global__ void sample_kernel(const float* __restrict__ logits,
                              float* __restrict__ actBuf,
                              float* __restrict__ outAction,
                              float* __restrict__ lpAcc,
                              float* __restrict__ entAcc,
                              uint32_t sk0, uint32_t sk1, int head)
{
    int warp = (blockIdx.x * blockDim.x + threadIdx.x) >> 5;
    int lane = threadIdx.x & 31;
    if (warp >= NB) return;
    int r = warp;

    float x0 = logits[r * 64 + lane];
    float x1 = logits[r * 64 + 32 + lane];

    float mx = fmaxf(x0, x1);
#pragma unroll
    for (int o = 16; o; o >>= 1) mx = fmaxf(mx, __shfl_xor_sync(0xffffffffu, mx, o));

    float s = expf(x0 - mx) + expf(x1 - mx);
#pragma unroll
    for (int o = 16; o; o >>= 1) s += __shfl_xor_sync(0xffffffffu, s, o);
    float lse = mx + logf(s);

    // entropy term: sum p * (lse - x) = -sum p*logp
    float t = expf(x0 - lse) * (lse - x0) + expf(x1 - lse) * (lse - x1);
#pragma unroll
    for (int o = 16; o; o >>= 1) t += __shfl_xor_sync(0xffffffffu, t, o);

    // gumbel-argmax
    float g0 = gumbel_for(sk0, sk1, (uint32_t)(r * 64 + lane));
    float g1 = gumbel_for(sk0, sk1, (uint32_t)(r * 64 + 32 + lane));
    float ya = x0 + g0, yb = x1 + g1;
    float y; int idx;
    if (ya >= yb) { y = ya; idx = lane; } else { y = yb; idx = lane + 32; }
#pragma unroll
    for (int o = 16; o; o >>= 1) {
        float oy = __shfl_xor_sync(0xffffffffu, y, o);
        int   oi = __shfl_xor_sync(0xffffffffu, idx, o);
        if (oy > y || (oy == y && oi < idx)) { y = oy; idx = oi; }
    }

    int src = idx & 31;
    float v0 = __shfl_sync(0xffffffffu, x0, src);
    float v1 = __shfl_sync(0xffffffffu, x1, src);
    float xw = (idx < 32) ? v0 : v1;

    if (lane == 0) {
        actBuf[r] = (float)idx;
        outAction[r * 8 + head] = (float)idx;
        lpAcc[r] += xw - lse;
        entAcc[r] += t;
    }
}

__global__ void init_kernel(float* __restrict__ lp, float* __restrict__ ent)
{
    int i = blockIdx.x * blockDim.x + threadIdx.x;
    if (i < NB) { lp[i] = 0.0f; ent[i] = 0.0f; }
}

__global__ void reduce_ent(const float* __restrict__ ent, float* __restrict__ out)
{
    __shared__ float sm[256];
    float s = 0.0f;
    for (int i = threadIdx.x; i < NB; i += 256) s += ent[i];
    sm[threadIdx.x] = s;
    __syncthreads();
    for (int o = 128; o; o >>= 1) {
        if (threadIdx.x < o) sm[threadIdx.x] += sm[threadIdx.x + o];
        __syncthreads();
    }
    if (threadIdx.x == 0) out[0] = sm[0];
}

// ------------------------------------------------------------------
// host launcher
// ------------------------------------------------------------------
extern "C" void kernel_launch(void* const* d_in, const int* in_sizes, int n_in,
                              void* d_out, int out_size)
{
    const float* actual    = (const float*)d_in[0];
    const float* objective = (const float*)d_in[1];
    const float* last      = (const float*)d_in[2];

    // episode_percentage may or may not be materialized as an input
    int base = 4;
    const int* epPtr = nullptr;
    if (in_sizes[3] == 1) epPtr = (const int*)d_in[3];
    else base = 3;

    const float* W1  = (const float*)d_in[base + 0];
    const float* b1  = (const float*)d_in[base + 1];
    const float* W2  = (const float*)d_in[base + 2];
    const float* b2  = (const float*)d_in[base + 3];
    const float* W3  = (const float*)d_in[base + 4];
    const float* b3  = (const float*)d_in[base + 5];
    const float* Wih = (const float*)d_in[base + 6];
    const float* Whh = (const float*)d_in[base + 7];
    const float* bih = (const float*)d_in[base + 8];
    const float* bhh = (const float*)d_in[base + 9];
    const float* h0  = (const float*)d_in[base + 10];
    const float* c0  = (const float*)d_in[base + 11];
    const float* dW1 = (const float*)d_in[base + 12];
    const float* db1 = (const float*)d_in[base + 13];

    const float* headW[8];
    const float* headb[8];
    const float* dWo;
    const float* dbo;
    if (n_in >= base + 32) {  // tuples flattened into separate inputs
        for (int i = 0; i < 8; i++) {
            headW[i] = (const float*)d_in[base + 14 + i];
            headb[i] = (const float*)d_in[base + 22 + i];
        }
        dWo = (const float*)d_in[base + 30];
        dbo = (const float*)d_in[base + 31];
    } else {                  // tuples stacked
        const float* hw = (const float*)d_in[base + 14];
        const float* hb = (const float*)d_in[base + 15];
        for (int i = 0; i < 8; i++) {
            headW[i] = hw + (size_t)i * 256 * 64;
            headb[i] = hb + (size_t)i * 64;
        }
        dWo = (const float*)d_in[base + 16];
        dbo = (const float*)d_in[base + 17];
    }

    const int D1 = in_sizes[base + 1];  // b1 length
    const int D2 = in_sizes[base + 3];  // b2 length

    float* scratch = nullptr;
    cudaGetSymbolAddress((void**)&scratch, g_scratch);
    float* x1v   = scratch + OFF_X1;
    float* x2v   = scratch + OFF_X2;
    float* x3v   = scratch + OFF_X3;
    float* gates = scratch + OFF_GATES;
    float* za    = scratch + OFF_ZA;
    float* zb    = scratch + OFF_ZB;
    float* z1b   = scratch + OFF_Z1;
    float* logb  = scratch + OFF_LOG;
    float* actb  = scratch + OFF_ACT;
    float* entb  = scratch + OFF_ENT;

    float* out  = (float*)d_out;
    float* lp   = out + NB * 8 + 1;   // log_probabilities
    float* entO = out + NB * 8;       // entropy scalar

    // --- JAX key chain (partitionable / fold-like split), host side ---
    uint32_t k0 = 0u, k1 = 42u, sk0[8], sk1[8];
    for (int t = 0; t < 8; t++) {
        uint32_t n0, n1, s0, s1;
        threefry2x32(k0, k1, 0u, 0u, &n0, &n1);  // new key
        threefry2x32(k0, k1, 0u, 1u, &s0, &s1);  // subkey for this head
        sk0[t] = s0; sk1[t] = s1;
        k0 = n0; k1 = n1;
    }

    dim3 blk(256);
    const int MBLK = NB / BM;  // 32

    init_kernel<<<(NB + 255) / 256, blk>>>(lp, entb);

    // encoder
    sgemm<<<dim3((D1 + BN - 1) / BN, MBLK), blk>>>(
        nullptr, 0, W1, D1, 1, b1, nullptr, x1v, D1, 9225, 1, 1,
        actual, objective, last, epPtr, nullptr);
    sgemm<<<dim3((D2 + BN - 1) / BN, MBLK), blk>>>(
        x1v, D1, W2, D2, 1, b2, nullptr, x2v, D2, D1, 1, 0,
        nullptr, nullptr, nullptr, nullptr, nullptr);
    sgemm<<<dim3(4, MBLK), blk>>>(
        x2v, D2, W3, 512, 1, b3, nullptr, x3v, 512, D2, 1, 0,
        nullptr, nullptr, nullptr, nullptr, nullptr);

    // LSTM gates: x @ Wih^T + bih + bhh, then += h0 @ Whh^T
    sgemm<<<dim3(16, MBLK), blk>>>(
        x3v, 512, Wih, 1, 512, bih, bhh, gates, 2048, 512, 0, 0,
        nullptr, nullptr, nullptr, nullptr, nullptr);
    sgemm<<<dim3(16, MBLK), blk>>>(
        h0, 512, Whh, 1, 512, nullptr, nullptr, gates, 2048, 512, 2, 0,
        nullptr, nullptr, nullptr, nullptr, nullptr);
    lstm_kernel<<<(NB * 512 + 255) / 256, blk>>>(gates, c0, za);

    // autoregressive decoder
    for (int t = 0; t < 8; t++) {
        float* zin  = (t & 1) ? zb : za;
        float* zout = (t & 1) ? za : zb;

        sgemm<<<dim3(2, MBLK), blk>>>(
            zin, 512, dW1, 256, 1, db1, nullptr, z1b, 256, 512, 1, 0,
            nullptr, nullptr, nullptr, nullptr, nullptr);
        sgemm<<<dim3(1, MBLK), blk>>>(
            z1b, 256, headW[t], 64, 1, headb[t], nullptr, logb, 64, 256, 0, 0,
            nullptr, nullptr, nullptr, nullptr, nullptr);
        sample_kernel<<<NB / 8, blk>>>(logb, actb, out, lp, entb,
                                       sk0[t], sk1[t], t);
        sgemm<<<dim3(4, MBLK), blk>>>(
            zin, 512, dWo, 512, 1, dbo, nullptr, zout, 512, 513, 1, 2,
            nullptr, nullptr, nullptr, nullptr, actb);
    }

    reduce_ent<<<1, blk>>>(entb, entO);
}

// round 4
// speedup vs baseline: 2.0143x; 1.9997x over previous
#include <cuda_runtime.h>
#include <stdint.h>
#include <math.h>

#define NB 4096

__device__ float g_scratch[336818176];

#define OFF_A1   0u
#define OFF_A2   113639424u
#define OFF_B1   156893184u
#define OFF_B2   256327680u
#define OFF_A3   272547840u
#define OFF_B3   289062912u
#define OFF_AL   291127296u
#define OFF_BL   303710208u
#define OFF_G    310001664u
#define OFF_ZA   318390272u
#define OFF_ZB   325074944u
#define OFF_Z1   331759616u
#define OFF_BD1  334905344u
#define OFF_BDO  335323136u
#define OFF_BH   336158720u
#define OFF_LOG  336551936u
#define OFF_ENT  336814080u

__device__ __forceinline__ uint32_t smem_u32(const void* p) {
    uint32_t a;
    asm("{ .reg .u64 t; cvta.to.shared.u64 t, %1; cvt.u32.u64 %0, t; }" : "=r"(a) : "l"(p));
    return a;
}
__device__ __forceinline__ float tf32r(float x) {
    uint32_t u; asm("cvt.rna.tf32.f32 %0, %1;" : "=r"(u) : "f"(x)); return __uint_as_float(u);
}

// ---------- threefry (JAX partitionable) ----------
__host__ __device__ __forceinline__ void threefry2x32(
    uint32_t k0, uint32_t k1, uint32_t x0, uint32_t x1, uint32_t* o0, uint32_t* o1)
{
    uint32_t ks0 = k0, ks1 = k1, ks2 = 0x1BD11BDAu ^ k0 ^ k1;
    x0 += ks0; x1 += ks1;
#define TF_ROUND(r) do { x0 += x1; x1 = (x1 << (r)) | (x1 >> (32 - (r))); x1 ^= x0; } while (0)
    TF_ROUND(13); TF_ROUND(15); TF_ROUND(26); TF_ROUND(6);
    x0 += ks1; x1 += ks2 + 1u;
    TF_ROUND(17); TF_ROUND(29); TF_ROUND(16); TF_ROUND(24);
    x0 += ks2; x1 += ks0 + 2u;
    TF_ROUND(13); TF_ROUND(15); TF_ROUND(26); TF_ROUND(6);
    x0 += ks0; x1 += ks1 + 3u;
    TF_ROUND(17); TF_ROUND(29); TF_ROUND(16); TF_ROUND(24);
    x0 += ks1; x1 += ks2 + 4u;
    TF_ROUND(13); TF_ROUND(15); TF_ROUND(26); TF_ROUND(6);
    x0 += ks2; x1 += ks0 + 5u;
#undef TF_ROUND
    *o0 = x0; *o1 = x1;
}
__device__ __forceinline__ float gumbel_for(uint32_t k0, uint32_t k1, uint32_t j)
{
    uint32_t o0, o1;
    threefry2x32(k0, k1, 0u, j, &o0, &o1);
    uint32_t bits = o0 ^ o1;
    uint32_t fb = (bits >> 9) | 0x3f800000u;
    float f = __uint_as_float(fb) - 1.0f;
    if (f == 0.0f) f = 1.1754943508222875e-38f;
    return -logf(-logf(f));
}

// ==================================================================
// tf32 mma.sync GEMM: 128x128 tile, K'=Kp (mult of 32), 256 threads
// A[m][k] row-major lda; B[n][k] row-major ldb (= col-major KxN)
// sec>0: relu'd 3-way split store [hi|lo|hi]; sec==0: plain store
// ==================================================================
__global__ void __launch_bounds__(256, 2)
mma_gemm(const float* __restrict__ A, int lda,
         const float* __restrict__ B, int ldb, int Brows, int Kp,
         const float* __restrict__ bias, const float* __restrict__ bias2,
         float* __restrict__ out, int ldOut, int sec,
         int Nreal, int NpadStore, int relu)
{
    extern __shared__ float sm[];
    const int tid  = threadIdx.x;
    const int bm   = blockIdx.y * 128;
    const int bn   = blockIdx.x * 128;
    const int lane = tid & 31;
    const int wid  = tid >> 5;
    const int wm   = wid >> 2;   // 0..1 (64 rows each)
    const int wn   = wid & 3;    // 0..3 (32 cols each)

    // smem: A[2][128][36], B[2][128][36]  (36-float padded rows)
    const uint32_t aBase = smem_u32(sm);
    const uint32_t bBase = aBase + 2u * 18432u;

    float acc[4][4][4];
#pragma unroll
    for (int i = 0; i < 4; i++)
#pragma unroll
        for (int j = 0; j < 4; j++)
#pragma unroll
            for (int e = 0; e < 4; e++) acc[i][j][e] = 0.0f;

    const int niter = Kp >> 5;

#define LOAD_TILE(buf, kt) do {                                               \
    int _k0 = (kt) * 32;                                                      \
    _Pragma("unroll")                                                         \
    for (int _i = 0; _i < 4; _i++) {                                          \
        int _idx = tid + _i * 256;                                            \
        int _row = _idx >> 3, _cj = _idx & 7;                                 \
        uint32_t _da = aBase + (buf) * 18432u + _row * 144u + _cj * 16u;      \
        const float* _ga = A + (size_t)(bm + _row) * lda + _k0 + _cj * 4;     \
        asm volatile("cp.async.cg.shared.global [%0], [%1], 16;"              \
                     :: "r"(_da), "l"(_ga));                                  \
        uint32_t _db = bBase + (buf) * 18432u + _row * 144u + _cj * 16u;      \
        int _ok = (bn + _row < Brows);                                        \
        const float* _gb = _ok ? (B + (size_t)(bn + _row) * ldb + _k0 + _cj * 4) : B; \
        int _sz = _ok ? 16 : 0;                                               \
        asm volatile("cp.async.cg.shared.global [%0], [%1], 16, %2;"          \
                     :: "r"(_db), "l"(_gb), "r"(_sz));                        \
    }                                                                         \
    asm volatile("cp.async.commit_group;" ::: "memory");                      \
} while (0)

    LOAD_TILE(0, 0);

    for (int kt = 0; kt < niter; kt++) {
        const int buf = kt & 1;
        if (kt + 1 < niter) {
            LOAD_TILE(buf ^ 1, kt + 1);
            asm volatile("cp.async.wait_group 1;" ::: "memory");
        } else {
            asm volatile("cp.async.wait_group 0;" ::: "memory");
        }
        __syncthreads();

        const float* as = sm + buf * 4608;
        const float* bs = sm + 2 * 4608 + buf * 4608;
#pragma unroll
        for (int ks = 0; ks < 4; ks++) {
            uint32_t a[4][4], b[4][2];
            const int r0 = wm * 64 + (lane >> 2);
            const int c0 = ks * 8 + (lane & 3);
#pragma unroll
            for (int mi = 0; mi < 4; mi++) {
                a[mi][0] = __float_as_uint(as[(r0 + mi * 16) * 36 + c0]);
                a[mi][1] = __float_as_uint(as[(r0 + mi * 16 + 8) * 36 + c0]);
                a[mi][2] = __float_as_uint(as[(r0 + mi * 16) * 36 + c0 + 4]);
                a[mi][3] = __float_as_uint(as[(r0 + mi * 16 + 8) * 36 + c0 + 4]);
            }
            const int n0 = wn * 32 + (lane >> 2);
#pragma unroll
            for (int ni = 0; ni < 4; ni++) {
                b[ni][0] = __float_as_uint(bs[(n0 + ni * 8) * 36 + c0]);
                b[ni][1] = __float_as_uint(bs[(n0 + ni * 8) * 36 + c0 + 4]);
            }
#pragma unroll
            for (int mi = 0; mi < 4; mi++)
#pragma unroll
                for (int ni = 0; ni < 4; ni++) {
                    asm volatile(
                        "mma.sync.aligned.m16n8k8.row.col.f32.tf32.tf32.f32 "
                        "{%0,%1,%2,%3}, {%4,%5,%6,%7}, {%8,%9}, {%0,%1,%2,%3};"
                        : "+f"(acc[mi][ni][0]), "+f"(acc[mi][ni][1]),
                          "+f"(acc[mi][ni][2]), "+f"(acc[mi][ni][3])
                        : "r"(a[mi][0]), "r"(a[mi][1]), "r"(a[mi][2]), "r"(a[mi][3]),
                          "r"(b[ni][0]), "r"(b[ni][1]));
                }
        }
        __syncthreads();
    }
#undef LOAD_TILE

    // epilogue
#pragma unroll
    for (int mi = 0; mi < 4; mi++)
#pragma unroll
        for (int ni = 0; ni < 4; ni++)
#pragma unroll
            for (int e = 0; e < 4; e++) {
                int m = bm + wm * 64 + mi * 16 + (lane >> 2) + ((e >= 2) ? 8 : 0);
                int n = bn + wn * 32 + ni * 8 + 2 * (lane & 3) + (e & 1);
                float v = 0.0f;
                if (n < Nreal) {
                    v = acc[mi][ni][e];
                    if (bias)  v += bias[n];
                    if (bias2) v += bias2[n];
                    if (relu)  v = fmaxf(v, 0.0f);
                }
                if (sec == 0) {
                    if (n < Nreal) out[(size_t)m * ldOut + n] = v;
                } else if (n < NpadStore) {
                    float hi = tf32r(v);
                    float* p = out + (size_t)m * ldOut;
                    p[n] = hi; p[sec + n] = v - hi; p[2 * sec + n] = hi;
                }
            }
}

// ---------- prep kernels ----------
__global__ void build_A1(const float* __restrict__ s0, const float* __restrict__ s1,
                         const float* __restrict__ s2, const int* __restrict__ epPtr,
                         float* __restrict__ A1)
{
    int k = blockIdx.x * 256 + threadIdx.x;
    int m = blockIdx.y;
    if (k >= 9248) return;
    float v = 0.0f;
    if (k < 4608)       v = s0[(size_t)m * 4608 + k];
    else if (k < 9216)  v = s1[(size_t)m * 4608 + (k - 4608)];
    else if (k < 9224)  v = s2[m * 8 + (k - 9216)];
    else if (k == 9224) v = epPtr ? (float)(*epPtr) : 0.0f;
    float hi = tf32r(v);
    size_t b = (size_t)m * 27744;
    A1[b + k] = hi; A1[b + 9248 + k] = v - hi; A1[b + 18496 + k] = hi;
}

// W[K,N] row-major -> out[n][3*Kpad] = [hi | hi | lo], zero padded
__global__ void tsplit(const float* __restrict__ W, int K, int N,
                       float* __restrict__ out, int Kpad)
{
    __shared__ float t[32][33];
    int kb = blockIdx.x * 32, nb = blockIdx.y * 32;
    int tx = threadIdx.x, ty = threadIdx.y;
#pragma unroll
    for (int r = 0; r < 4; r++) {
        int k = kb + ty + r * 8, n = nb + tx;
        t[ty + r * 8][tx] = (k < K && n < N) ? W[(size_t)k * N + n] : 0.0f;
    }
    __syncthreads();
#pragma unroll
    for (int r = 0; r < 4; r++) {
        int n = nb + ty + r * 8, k = kb + tx;
        float v = t[tx][ty + r * 8];
        float hi = tf32r(v);
        size_t b = (size_t)n * (3 * (size_t)Kpad);
        out[b + k] = hi; out[b + Kpad + k] = hi; out[b + 2 * Kpad + k] = v - hi;
    }
}

__global__ void split_lstm(const float* __restrict__ Wih, const float* __restrict__ Whh,
                           float* __restrict__ out)
{
    int idx = blockIdx.x * 256 + threadIdx.x;
    if (idx >= 2048 * 512) return;
    int n = idx >> 9, k = idx & 511;
    float a = Wih[idx], c = Whh[idx];
    float ah = tf32r(a), ch = tf32r(c);
    size_t b = (size_t)n * 3072;
    out[b + k] = ah;            out[b + 512 + k] = ch;
    out[b + 1024 + k] = ah;     out[b + 1536 + k] = ch;
    out[b + 2048 + k] = a - ah; out[b + 2560 + k] = c - ch;
}

__global__ void h0split(const float* __restrict__ h0, float* __restrict__ AL)
{
    int idx = blockIdx.x * 256 + threadIdx.x;
    if (idx >= NB * 512) return;
    int m = idx >> 9, c = idx & 511;
    float v = h0[idx];
    float hi = tf32r(v);
    size_t b = (size_t)m * 3072;
    AL[b + 512 + c] = hi; AL[b + 1536 + c] = v - hi; AL[b + 2560 + c] = hi;
}

__global__ void lstm_kernel(const float* __restrict__ gates,
                            const float* __restrict__ c0, float* __restrict__ za)
{
    int i = blockIdx.x * blockDim.x + threadIdx.x;
    if (i >= NB * 512) return;
    int m = i >> 9, c = i & 511;
    const float* gr = gates + (size_t)m * 2048;
    float gi = gr[c], gf = gr[512 + c], gg = gr[1024 + c], go = gr[1536 + c];
    float si = 1.0f / (1.0f + expf(-gi));
    float sf = 1.0f / (1.0f + expf(-gf));
    float so = 1.0f / (1.0f + expf(-go));
    float cc = sf * c0[i] + si * tanhf(gg);
    float z = so * tanhf(cc);
    float hi = tf32r(z);
    size_t b = (size_t)m * 1632;
    za[b + c] = hi; za[b + 544 + c] = z - hi; za[b + 1088 + c] = hi;
}

__global__ void sample_kernel(const float* __restrict__ logits,
                              float* __restrict__ zin,
                              float* __restrict__ outAction,
                              float* __restrict__ lpAcc,
                              float* __restrict__ entAcc,
                              uint32_t sk0, uint32_t sk1, int head)
{
    int warp = (blockIdx.x * blockDim.x + threadIdx.x) >> 5;
    int lane = threadIdx.x & 31;
    if (warp >= NB) return;
    int r = warp;

    float x0 = logits[r * 64 + lane];
    float x1 = logits[r * 64 + 32 + lane];

    float mx = fmaxf(x0, x1);
#pragma unroll
    for (int o = 16; o; o >>= 1) mx = fmaxf(mx, __shfl_xor_sync(0xffffffffu, mx, o));
    float s = expf(x0 - mx) + expf(x1 - mx);
#pragma unroll
    for (int o = 16; o; o >>= 1) s += __shfl_xor_sync(0xffffffffu, s, o);
    float lse = mx + logf(s);

    float t = expf(x0 - lse) * (lse - x0) + expf(x1 - lse) * (lse - x1);
#pragma unroll
    for (int o = 16; o; o >>= 1) t += __shfl_xor_sync(0xffffffffu, t, o);

    float g0 = gumbel_for(sk0, sk1, (uint32_t)(r * 64 + lane));
    float g1 = gumbel_for(sk0, sk1, (uint32_t)(r * 64 + 32 + lane));
    float ya = x0 + g0, yb = x1 + g1;
    float y; int idx;
    if (ya >= yb) { y = ya; idx = lane; } else { y = yb; idx = lane + 32; }
#pragma unroll
    for (int o = 16; o; o >>= 1) {
        float oy = __shfl_xor_sync(0xffffffffu, y, o);
        int   oi = __shfl_xor_sync(0xffffffffu, idx, o);
        if (oy > y || (oy == y && oi < idx)) { y = oy; idx = oi; }
    }
    int src = idx & 31;
    float v0 = __shfl_sync(0xffffffffu, x0, src);
    float v1 = __shfl_sync(0xffffffffu, x1, src);
    float xw = (idx < 32) ? v0 : v1;

    if (lane == 0) {
        float a = (float)idx;
        size_t b = (size_t)r * 1632;
        zin[b + 512] = a;           // hi section
        zin[b + 544 + 512] = 0.0f;  // lo section (act exact in tf32)
        zin[b + 1088 + 512] = a;    // hi section
        outAction[r * 8 + head] = a;
        lpAcc[r] += xw - lse;
        entAcc[r] += t;
    }
}

__global__ void init_kernel(float* __restrict__ lp, float* __restrict__ ent)
{
    int i = blockIdx.x * blockDim.x + threadIdx.x;
    if (i < NB) { lp[i] = 0.0f; ent[i] = 0.0f; }
}

__global__ void reduce_ent(const float* __restrict__ ent, float* __restrict__ out)
{
    __shared__ float sm[256];
    float s = 0.0f;
    for (int i = threadIdx.x; i < NB; i += 256) s += ent[i];
    sm[threadIdx.x] = s;
    __syncthreads();
    for (int o = 128; o; o >>= 1) {
        if (threadIdx.x < o) sm[threadIdx.x] += sm[threadIdx.x + o];
        __syncthreads();
    }
    if (threadIdx.x == 0) out[0] = sm[0];
}

// ---------- host launcher ----------
extern "C" void kernel_launch(void* const* d_in, const int* in_sizes, int n_in,
                              void* d_out, int out_size)
{
    const float* actual    = (const float*)d_in[0];
    const float* objective = (const float*)d_in[1];
    const float* last      = (const float*)d_in[2];

    int base = 4;
    const int* epPtr = nullptr;
    if (in_sizes[3] == 1) epPtr = (const int*)d_in[3];
    else base = 3;

    const float* W1  = (const float*)d_in[base + 0];
    const float* b1  = (const float*)d_in[base + 1];
    const float* W2  = (const float*)d_in[base + 2];
    const float* b2  = (const float*)d_in[base + 3];
    const float* W3  = (const float*)d_in[base + 4];
    const float* b3  = (const float*)d_in[base + 5];
    const float* Wih = (const float*)d_in[base + 6];
    const float* Whh = (const float*)d_in[base + 7];
    const float* bih = (const float*)d_in[base + 8];
    const float* bhh = (const float*)d_in[base + 9];
    const float* h0  = (const float*)d_in[base + 10];
    const float* c0  = (const float*)d_in[base + 11];
    const float* dW1 = (const float*)d_in[base + 12];
    const float* db1 = (const float*)d_in[base + 13];

    const float* headW[8];
    const float* headb[8];
    const float* dWo;
    const float* dbo;
    if (n_in >= base + 32) {
        for (int i = 0; i < 8; i++) {
            headW[i] = (const float*)d_in[base + 14 + i];
            headb[i] = (const float*)d_in[base + 22 + i];
        }
        dWo = (const float*)d_in[base + 30];
        dbo = (const float*)d_in[base + 31];
    } else {
        const float* hw = (const float*)d_in[base + 14];
        const float* hb = (const float*)d_in[base + 15];
        for (int i = 0; i < 8; i++) {
            headW[i] = hw + (size_t)i * 256 * 64;
            headb[i] = hb + (size_t)i * 64;
        }
        dWo = (const float*)d_in[base + 16];
        dbo = (const float*)d_in[base + 17];
    }
    const int D1 = in_sizes[base + 1];  // 3518
    const int D2 = in_sizes[base + 3];  // 1342

    float* sc = nullptr;
    cudaGetSymbolAddress((void**)&sc, g_scratch);
    float* A1 = sc + OFF_A1;   float* A2 = sc + OFF_A2;
    float* B1 = sc + OFF_B1;   float* B2 = sc + OFF_B2;
    float* A3 = sc + OFF_A3;   float* B3 = sc + OFF_B3;
    float* AL = sc + OFF_AL;   float* BL = sc + OFF_BL;
    float* gates = sc + OFF_G;
    float* za = sc + OFF_ZA;   float* zb = sc + OFF_ZB;
    float* Z1 = sc + OFF_Z1;
    float* BD1 = sc + OFF_BD1; float* BDO = sc + OFF_BDO;
    float* BH = sc + OFF_BH;
    float* logb = sc + OFF_LOG;
    float* entb = sc + OFF_ENT;

    float* out  = (float*)d_out;
    float* lp   = out + NB * 8 + 1;
    float* entO = out + NB * 8;

    uint32_t k0 = 0u, k1 = 42u, sk0[8], sk1[8];
    for (int t = 0; t < 8; t++) {
        uint32_t n0, n1, s0, s1;
        threefry2x32(k0, k1, 0u, 0u, &n0, &n1);
        threefry2x32(k0, k1, 0u, 1u, &s0, &s1);
        sk0[t] = s0; sk1[t] = s1;
        k0 = n0; k1 = n1;
    }

    const int SMEM = 4 * 18432;  // 73728 bytes
    cudaFuncSetAttribute(mma_gemm, cudaFuncAttributeMaxDynamicSharedMemorySize, SMEM);

    dim3 blk(256);
    dim3 tsb(32, 8);

    init_kernel<<<(NB + 255) / 256, blk>>>(lp, entb);

    // weight prep
    tsplit<<<dim3(289, 112), tsb>>>(W1, 9225, D1, B1, 9248);
    tsplit<<<dim3(110, 48),  tsb>>>(W2, D1, D2, B2, 3520);
    tsplit<<<dim3(42, 16),   tsb>>>(W3, D2, 512, B3, 1344);
    split_lstm<<<(2048 * 512 + 255) / 256, blk>>>(Wih, Whh, BL);
    h0split<<<(NB * 512 + 255) / 256, blk>>>(h0, AL);
    tsplit<<<dim3(17, 8),  tsb>>>(dW1, 512, 256, BD1, 544);
    tsplit<<<dim3(17, 16), tsb>>>(dWo, 513, 512, BDO, 544);
    for (int t = 0; t < 8; t++)
        tsplit<<<dim3(8, 2), tsb>>>(headW[t], 256, 64, BH + (size_t)t * 49152, 256);
    build_A1<<<dim3(37, 4096), blk>>>(actual, objective, last, epPtr, A1);

    // encoder
    mma_gemm<<<dim3(28, 32), blk, SMEM>>>(A1, 27744, B1, 27744, 3584, 27744,
        b1, nullptr, A2, 10560, 3520, D1, 3520, 1);
    mma_gemm<<<dim3(11, 32), blk, SMEM>>>(A2, 10560, B2, 10560, 1536, 10560,
        b2, nullptr, A3, 4032, 1344, D2, 1344, 1);
    mma_gemm<<<dim3(4, 32), blk, SMEM>>>(A3, 4032, B3, 4032, 512, 4032,
        b3, nullptr, AL, 3072, 1024, 512, 512, 1);

    // LSTM
    mma_gemm<<<dim3(16, 32), blk, SMEM>>>(AL, 3072, BL, 3072, 2048, 3072,
        bih, bhh, gates, 2048, 0, 2048, 0, 0);
    lstm_kernel<<<(NB * 512 + 255) / 256, blk>>>(gates, c0, za);

    // decoder
    for (int t = 0; t < 8; t++) {
        float* zin  = (t & 1) ? zb : za;
        float* zout = (t & 1) ? za : zb;
        mma_gemm<<<dim3(2, 32), blk, SMEM>>>(zin, 1632, BD1, 1632, 256, 1632,
            db1, nullptr, Z1, 768, 256, 256, 256, 1);
        mma_gemm<<<dim3(1, 32), blk, SMEM>>>(Z1, 768, BH + (size_t)t * 49152, 768, 64, 768,
            headb[t], nullptr, logb, 64, 0, 64, 0, 0);
        sample_kernel<<<NB / 8, blk>>>(logb, zin, out, lp, entb, sk0[t], sk1[t], t);
        mma_gemm<<<dim3(4, 32), blk, SMEM>>>(zin, 1632, BDO, 1632, 512, 1632,
            dbo, nullptr, zout, 1632, 544, 512, 512, 1);
    }

    reduce_ent<<<1, blk>>>(entb, entO);
}